// round 16
// baseline (speedup 1.0000x reference)
#include <cuda_runtime.h>

#define TPB 128      // threads per block == targets per block
#define SCHUNK 4     // sources per block (grid.y splits S) = 2 packed lane-pairs
#define NLP (SCHUNK / 2)
#define SMAX 8192

typedef unsigned long long ull;

__device__ __forceinline__ ull pack2(float lo, float hi) {
    ull r; asm("mov.b64 %0, {%1, %2};" : "=l"(r) : "f"(lo), "f"(hi)); return r;
}
__device__ __forceinline__ void unpack2(ull v, float& lo, float& hi) {
    asm("mov.b64 {%0, %1}, %2;" : "=f"(lo), "=f"(hi) : "l"(v));
}
__device__ __forceinline__ ull fma2(ull a, ull b, ull c) {
    ull d; asm("fma.rn.f32x2 %0, %1, %2, %3;" : "=l"(d) : "l"(a), "l"(b), "l"(c)); return d;
}
// packed silu on pre-halved input: h = b + b*tanh(b).
__device__ __forceinline__ ull silu_packed(ull b) {
    ull h;
    asm("{\n\t"
        ".reg .f32 lo, hi, tl, th;\n\t"
        ".reg .b64 tt;\n\t"
        "mov.b64 {lo, hi}, %1;\n\t"
        "tanh.approx.f32 tl, lo;\n\t"
        "tanh.approx.f32 th, hi;\n\t"
        "mov.b64 tt, {tl, th};\n\t"
        "fma.rn.f32x2 %0, %1, tt, %1;\n\t"
        "}" : "=l"(h) : "l"(b));
    return h;
}
// epilogue tanh: HW approx (1 MUFU). Accuracy validated: rel_err ~3e-6.
__device__ __forceinline__ float tanh_apx(float x) {
    float y; asm("tanh.approx.f32 %0, %1;" : "=f"(y) : "f"(x)); return y;
}

struct __align__(16) SrcData {
    float x, y, z, area;       // coords pre-scaled by 1/refL
    float logn, nhx, nhy, nhz; // 0.5*ln(n2), unit normal
    float w, pad0, pad1, pad2; // strength
};

// ---- device-global scratch (prep results) ----
__device__ SrcData g_src[SMAX];
__device__ float   g_aconst[SMAX * 64];       // per-(source,j) folded constant (pre-halved)
__device__ __align__(16) ull g_wrec[64][10];  // per-j: w1log,q1,q2,q3,q4 (pre-halved), v0..v3, [slot9: b2 for j<4]

// constant-bank copy: ONLY the layer-1 record is hot here now (3 LDC/j);
// layer-2 v's are served from SMEM to split load across const-port + LSU.
__constant__ __align__(16) ull c_wrec[64 * 10];

// ---- single fused prep kernel: grid.x = SP blocks, 64 threads (j) ----
__global__ void __launch_bounds__(64) prep_all(
    const float* __restrict__ refL,
    const float* __restrict__ sp,
    const float* __restrict__ ss,
    const float* __restrict__ sa,
    const float* __restrict__ sn,
    const float* __restrict__ W1,
    const float* __restrict__ b1,
    const float* __restrict__ W2,
    const float* __restrict__ b2,
    float* __restrict__ out,
    int S, int SP, int out_size)
{
    const int s = blockIdx.x;
    const int j = threadIdx.x;

    // zero the output (poisoned by harness)
    for (int oz = s * 64 + j; oz < out_size; oz += SP * 64) out[oz] = 0.0f;

    // per-source record (computed redundantly by all 64 threads; cheap)
    SrcData d;
    if (s < S) {
        float invL = 1.0f / refL[0];
        float nx = sn[3 * s], ny = sn[3 * s + 1], nz = sn[3 * s + 2];
        float n2 = fmaf(nx, nx, fmaf(ny, ny, nz * nz)) + 1e-16f;
        float invn = rsqrtf(n2);
        d.x = sp[3 * s] * invL;
        d.y = sp[3 * s + 1] * invL;
        d.z = sp[3 * s + 2] * invL;
        d.area = sa[s];
        d.logn = 0.5f * __logf(n2);
        d.nhx = nx * invn; d.nhy = ny * invn; d.nhz = nz * invn;
        d.w = ss[s];
    } else {
        d.x = 0.f; d.y = 0.f; d.z = 0.f; d.area = 0.f;
        d.logn = 0.f; d.nhx = 1.f; d.nhy = 0.f; d.nhz = 0.f;
        d.w = 0.f;  // zero strength -> no contribution
    }
    d.pad0 = d.pad1 = d.pad2 = 0.f;
    if (j == 0) g_src[s] = d;

    // weight records (block 0 only)
    // Legendre fold: w3*P1+w4*P2+w5*P3+w6*P4 =
    //   (w3-1.5w5)c + (1.5w4-3.75w6)c^2 + 2.5w5 c^3 + 4.375w6 c^4 + (-0.5w4+0.375w6)
    if (s == 0) {
        float w3 = W1[3 * 64 + j], w4 = W1[4 * 64 + j];
        float w5 = W1[5 * 64 + j], w6 = W1[6 * 64 + j];
        // pre-halved for silu trick AND pre-scaled by 0.5*ln(2) (kernel feeds log2(r2))
        float w1log = 0.5f * 0.34657359027997264f * W1[1 * 64 + j];
        g_wrec[j][0] = pack2(w1log, w1log);
        float q1 = 0.5f * (w3 - 1.5f * w5);
        float q2 = 0.5f * (1.5f * w4 - 3.75f * w6);
        float q3 = 0.5f * (2.5f * w5);
        float q4 = 0.5f * (4.375f * w6);
        g_wrec[j][1] = pack2(q1, q1);
        g_wrec[j][2] = pack2(q2, q2);
        g_wrec[j][3] = pack2(q3, q3);
        g_wrec[j][4] = pack2(q4, q4);
        #pragma unroll
        for (int k = 0; k < 4; k++) {
            float v = W2[j * 4 + k];
            g_wrec[j][5 + k] = pack2(v, v);
        }
        if (j < 4) { float v = b2[j]; g_wrec[j][9] = pack2(v, v); }
        else g_wrec[j][9] = 0ull;
    }

    // folded per-(source,j) constant: b1 + poly-const + area*w0 + logn*w2 (pre-halved)
    float qc = fmaf(-0.5f, W1[4 * 64 + j], 0.375f * W1[6 * 64 + j]);
    float v = b1[j] + qc;
    v = fmaf(d.area, W1[0 * 64 + j], v);
    v = fmaf(d.logn, W1[2 * 64 + j], v);
    g_aconst[s * 64 + j] = 0.5f * v;
}

// (128,7): 7 blocks/SM, 3.95 waves. Weight loads split: layer-1 poly coeffs
// via constant port (3 LDC/j), layer-2 v's via SMEM (2 LDS.128/j) -> the
// half-rate constant port (LDC floor=8) stops being the issue ceiling.
__global__ void __launch_bounds__(TPB, 7) bh_kernel(
    const float* __restrict__ refL,
    const float* __restrict__ tp,
    float* __restrict__ out,
    int T)
{
    __shared__ ull sA[64][NLP];                    // 1 KB  packed aconst pairs
    __shared__ __align__(16) ull sV[64][4];        // 2 KB  layer-2 weights (dup pairs)
    __shared__ SrcData ssrc[SCHUNK];

    const int tid = threadIdx.x;
    const int s0 = blockIdx.y * SCHUNK;

    {
        int j = tid >> 1, l = tid & 1;             // 128 entries == TPB
        sA[j][l] = pack2(g_aconst[(s0 + 2 * l) * 64 + j],
                         g_aconst[(s0 + 2 * l + 1) * 64 + j]);
    }
    #pragma unroll
    for (int i = tid; i < 64 * 4; i += TPB) {      // 2 per thread
        sV[i >> 2][i & 3] = g_wrec[i >> 2][5 + (i & 3)];
    }
    if (tid < SCHUNK) ssrc[tid] = g_src[s0 + tid];
    __syncthreads();

    const int t = blockIdx.x * TPB + tid;
    if (t >= T) return;

    const float invL = 1.0f / refL[0];
    const float tx = tp[3 * t] * invL;
    const float ty = tp[3 * t + 1] * invL;
    const float tz = tp[3 * t + 2] * invL;

    // ---- front: geometry for 4 sources; keep only ir + packed (log2r2, c)
    float ir[SCHUNK];
    ull LOGR[NLP], C[NLP];
    ull O0[NLP], O1[NLP], O2[NLP], O3[NLP];
    {
        float lr[SCHUNK], cc[SCHUNK];
        #pragma unroll
        for (int u = 0; u < SCHUNK; u++) {
            const SrcData sd = ssrc[u];
            float dx = tx - sd.x, dy = ty - sd.y, dz = tz - sd.z;
            float r2 = fmaf(dx, dx, fmaf(dy, dy, fmaf(dz, dz, 1e-16f)));
            float irr = rsqrtf(r2);
            cc[u] = (dx * sd.nhx + dy * sd.nhy + dz * sd.nhz) * irr;
            lr[u] = __log2f(r2);    // ln->log2 scale folded into w1log
            ir[u] = irr;
        }
        #pragma unroll
        for (int l = 0; l < NLP; l++) {
            LOGR[l] = pack2(lr[2*l], lr[2*l+1]);
            C[l]    = pack2(cc[2*l], cc[2*l+1]);
            O0[l] = c_wrec[0 * 10 + 9];   // b2[0]
            O1[l] = c_wrec[1 * 10 + 9];   // b2[1]
            O2[l] = c_wrec[2 * 10 + 9];   // b2[2]
            O3[l] = c_wrec[3 * 10 + 9];   // b2[3]
        }
    }

    // ---- fused MLP: Horner in c; layer-1 coeffs via constant port (3 LDC),
    //      layer-2 v's via SMEM (2 LDS.128), aconst via LDS — port-balanced
    #pragma unroll 4
    for (int j = 0; j < 64; j++) {
        const ulonglong2* wp = (const ulonglong2*)&c_wrec[j * 10];
        ulonglong2 p0 = wp[0];   // w1log, q1
        ulonglong2 p1 = wp[1];   // q2, q3
        ull q4 = c_wrec[j * 10 + 4];
        const ulonglong2* vp = (const ulonglong2*)&sV[j][0];
        ulonglong2 v01 = vp[0];  // v0, v1
        ulonglong2 v23 = vp[1];  // v2, v3
        #pragma unroll
        for (int l = 0; l < NLP; l++) {
            // base = A + log2r2*w1log ; poly = c*(q1 + c*(q2 + c*(q3 + c*q4)))
            ull base = fma2(LOGR[l], p0.x, sA[j][l]);
            ull pq = fma2(C[l], q4, p1.y);        // q3 + c*q4
            pq = fma2(C[l], pq, p1.x);            // q2 + ...
            pq = fma2(C[l], pq, p0.y);            // q1 + ...
            ull b = fma2(C[l], pq, base);
            ull h = silu_packed(b);               // silu(2b) = b + b*tanh(b)
            O0[l] = fma2(h, v01.x, O0[l]);
            O1[l] = fma2(h, v01.y, O1[l]);
            O2[l] = fma2(h, v23.x, O2[l]);
            O3[l] = fma2(h, v23.y, O3[l]);
        }
    }

    // ---- epilogue: tanh (HW approx), decay weighting, accumulate
    float o0[SCHUNK], o1[SCHUNK], o2[SCHUNK], o3[SCHUNK];
    #pragma unroll
    for (int l = 0; l < NLP; l++) {
        unpack2(O0[l], o0[2*l], o0[2*l+1]);
        unpack2(O1[l], o1[2*l], o1[2*l+1]);
        unpack2(O2[l], o2[2*l], o2[2*l+1]);
        unpack2(O3[l], o3[2*l], o3[2*l+1]);
    }

    float acc0 = 0.f, acc1 = 0.f, acc2 = 0.f, acc3 = 0.f;
    #pragma unroll
    for (int u = 0; u < SCHUNK; u++) {
        const SrcData sd = ssrc[u];
        float t0 = tanh_apx(o0[u]);
        float t1 = tanh_apx(o1[u]);
        float t2 = tanh_apx(o2[u]);
        float t3 = tanh_apx(o3[u]);
        float irr = ir[u];
        float dx = tx - sd.x, dy = ty - sd.y, dz = tz - sd.z;
        float wir = sd.w * irr;              // w * inv_r   (scalar decay, D=3)
        acc0 = fmaf(wir, t0, acc0);
        float wv = wir * irr;                // w * inv_r^2 (vector decay)
        float rhx = dx * irr, rhy = dy * irr, rhz = dz * irr;
        float cx = rhy * sd.nhz - rhz * sd.nhy;
        float cy = rhz * sd.nhx - rhx * sd.nhz;
        float cz = rhx * sd.nhy - rhy * sd.nhx;
        acc1 = fmaf(wv, fmaf(t1, rhx, fmaf(t2, sd.nhx, t3 * cx)), acc1);
        acc2 = fmaf(wv, fmaf(t1, rhy, fmaf(t2, sd.nhy, t3 * cy)), acc2);
        acc3 = fmaf(wv, fmaf(t1, rhz, fmaf(t2, sd.nhz, t3 * cz)), acc3);
    }

    // one vector reduction instead of 4 scalar atomics
    asm volatile("red.global.add.v4.f32 [%0], {%1, %2, %3, %4};"
                 :: "l"(out + 4 * t), "f"(acc0), "f"(acc1), "f"(acc2), "f"(acc3)
                 : "memory");
}

extern "C" void kernel_launch(void* const* d_in, const int* in_sizes, int n_in,
                              void* d_out, int out_size) {
    const float* refL = (const float*)d_in[0];
    const float* sp   = (const float*)d_in[1];
    const float* tp   = (const float*)d_in[2];
    const float* ss   = (const float*)d_in[3];
    const float* sa   = (const float*)d_in[4];
    const float* sn   = (const float*)d_in[5];
    const float* W1   = (const float*)d_in[6];
    const float* b1   = (const float*)d_in[7];
    const float* W2   = (const float*)d_in[8];
    const float* b2   = (const float*)d_in[9];
    float* out = (float*)d_out;

    int S = in_sizes[3];          // source_strengths element count
    int T = in_sizes[2] / 3;      // target_points is (T, 3)
    int SP = ((S + SCHUNK - 1) / SCHUNK) * SCHUNK;
    if (SP > SMAX) SP = SMAX;

    prep_all<<<SP, 64>>>(refL, sp, ss, sa, sn, W1, b1, W2, b2, out, S, SP, out_size);

    // copy folded weight record into the constant bank (D2D, graph-capturable)
    void* wsrc = nullptr;
    cudaGetSymbolAddress(&wsrc, g_wrec);
    cudaMemcpyToSymbolAsync(c_wrec, wsrc, sizeof(ull) * 64 * 10, 0,
                            cudaMemcpyDeviceToDevice);

    dim3 grid((T + TPB - 1) / TPB, SP / SCHUNK);
    bh_kernel<<<grid, TPB>>>(refL, tp, out, T);
}

// round 17
// speedup vs baseline: 1.1835x; 1.1835x over previous
#include <cuda_runtime.h>

#define TPB 128      // threads per block == targets per block
#define SCHUNK 6     // sources per block = 3 packed lane-pairs (ILP)
#define NLP (SCHUNK / 2)
#define SMAX 8192

typedef unsigned long long ull;

__device__ __forceinline__ ull pack2(float lo, float hi) {
    ull r; asm("mov.b64 %0, {%1, %2};" : "=l"(r) : "f"(lo), "f"(hi)); return r;
}
__device__ __forceinline__ void unpack2(ull v, float& lo, float& hi) {
    asm("mov.b64 {%0, %1}, %2;" : "=f"(lo), "=f"(hi) : "l"(v));
}
__device__ __forceinline__ ull fma2(ull a, ull b, ull c) {
    ull d; asm("fma.rn.f32x2 %0, %1, %2, %3;" : "=l"(d) : "l"(a), "l"(b), "l"(c)); return d;
}
// packed silu on pre-halved input: h = b + b*tanh(b).
__device__ __forceinline__ ull silu_packed(ull b) {
    ull h;
    asm("{\n\t"
        ".reg .f32 lo, hi, tl, th;\n\t"
        ".reg .b64 tt;\n\t"
        "mov.b64 {lo, hi}, %1;\n\t"
        "tanh.approx.f32 tl, lo;\n\t"
        "tanh.approx.f32 th, hi;\n\t"
        "mov.b64 tt, {tl, th};\n\t"
        "fma.rn.f32x2 %0, %1, tt, %1;\n\t"
        "}" : "=l"(h) : "l"(b));
    return h;
}
// epilogue tanh: HW approx (1 MUFU). Accuracy validated: rel_err ~3e-6.
__device__ __forceinline__ float tanh_apx(float x) {
    float y; asm("tanh.approx.f32 %0, %1;" : "=f"(y) : "f"(x)); return y;
}

struct __align__(16) SrcData {
    float x, y, z, area;       // coords pre-scaled by 1/refL
    float logn, nhx, nhy, nhz; // 0.5*ln(n2), unit normal
    float w, pad0, pad1, pad2; // strength
};

// ---- device-global scratch (prep results) ----
__device__ SrcData g_src[SMAX];
__device__ float   g_aconst[SMAX * 64];       // per-(source,j) folded constant (pre-halved)
__device__ __align__(16) ull g_wrec[64][10];  // per-j: w1log,q1,q2,q3,q4 (pre-halved), v0..v3, [slot9: b2 for j<4]

// constant-bank copy of the weight record: uniform loads in the hot loop
__constant__ __align__(16) ull c_wrec[64 * 10];

// ---- single fused prep kernel: grid.x = SP blocks, 64 threads (j) ----
__global__ void __launch_bounds__(64) prep_all(
    const float* __restrict__ refL,
    const float* __restrict__ sp,
    const float* __restrict__ ss,
    const float* __restrict__ sa,
    const float* __restrict__ sn,
    const float* __restrict__ W1,
    const float* __restrict__ b1,
    const float* __restrict__ W2,
    const float* __restrict__ b2,
    float* __restrict__ out,
    int S, int SP, int out_size)
{
    const int s = blockIdx.x;
    const int j = threadIdx.x;

    // zero the output (poisoned by harness)
    for (int oz = s * 64 + j; oz < out_size; oz += SP * 64) out[oz] = 0.0f;

    // per-source record (computed redundantly by all 64 threads; cheap)
    SrcData d;
    if (s < S) {
        float invL = 1.0f / refL[0];
        float nx = sn[3 * s], ny = sn[3 * s + 1], nz = sn[3 * s + 2];
        float n2 = fmaf(nx, nx, fmaf(ny, ny, nz * nz)) + 1e-16f;
        float invn = rsqrtf(n2);
        d.x = sp[3 * s] * invL;
        d.y = sp[3 * s + 1] * invL;
        d.z = sp[3 * s + 2] * invL;
        d.area = sa[s];
        d.logn = 0.5f * __logf(n2);
        d.nhx = nx * invn; d.nhy = ny * invn; d.nhz = nz * invn;
        d.w = ss[s];
    } else {
        d.x = 0.f; d.y = 0.f; d.z = 0.f; d.area = 0.f;
        d.logn = 0.f; d.nhx = 1.f; d.nhy = 0.f; d.nhz = 0.f;
        d.w = 0.f;  // zero strength -> no contribution
    }
    d.pad0 = d.pad1 = d.pad2 = 0.f;
    if (j == 0) g_src[s] = d;

    // weight records (block 0 only)
    // Legendre fold: w3*P1+w4*P2+w5*P3+w6*P4 =
    //   (w3-1.5w5)c + (1.5w4-3.75w6)c^2 + 2.5w5 c^3 + 4.375w6 c^4 + (-0.5w4+0.375w6)
    if (s == 0) {
        float w3 = W1[3 * 64 + j], w4 = W1[4 * 64 + j];
        float w5 = W1[5 * 64 + j], w6 = W1[6 * 64 + j];
        // pre-halved for silu trick AND pre-scaled by 0.5*ln(2) (kernel feeds log2(r2))
        float w1log = 0.5f * 0.34657359027997264f * W1[1 * 64 + j];
        g_wrec[j][0] = pack2(w1log, w1log);
        float q1 = 0.5f * (w3 - 1.5f * w5);
        float q2 = 0.5f * (1.5f * w4 - 3.75f * w6);
        float q3 = 0.5f * (2.5f * w5);
        float q4 = 0.5f * (4.375f * w6);
        g_wrec[j][1] = pack2(q1, q1);
        g_wrec[j][2] = pack2(q2, q2);
        g_wrec[j][3] = pack2(q3, q3);
        g_wrec[j][4] = pack2(q4, q4);
        #pragma unroll
        for (int k = 0; k < 4; k++) {
            float v = W2[j * 4 + k];
            g_wrec[j][5 + k] = pack2(v, v);
        }
        if (j < 4) { float v = b2[j]; g_wrec[j][9] = pack2(v, v); }
        else g_wrec[j][9] = 0ull;
    }

    // folded per-(source,j) constant: b1 + poly-const + area*w0 + logn*w2 (pre-halved)
    float qc = fmaf(-0.5f, W1[4 * 64 + j], 0.375f * W1[6 * 64 + j]);
    float v = b1[j] + qc;
    v = fmaf(d.area, W1[0 * 64 + j], v);
    v = fmaf(d.logn, W1[2 * 64 + j], v);
    g_aconst[s * 64 + j] = 0.5f * v;
}

// SCHUNK=6: three independent packed chains per thread (fma-latency cover),
// per-j constant loads amortized over 6 pairs. (128,6): 85-reg cap, 6 blocks/SM,
// 2736 blocks -> 3.08 waves.
__global__ void __launch_bounds__(TPB, 6) bh_kernel(
    const float* __restrict__ refL,
    const float* __restrict__ tp,
    float* __restrict__ out,
    int T)
{
    __shared__ ull sA[64][NLP];                // 1.5 KB  packed aconst pairs
    __shared__ SrcData ssrc[SCHUNK];

    const int tid = threadIdx.x;
    const int s0 = blockIdx.y * SCHUNK;

    for (int i = tid; i < 64 * NLP; i += TPB) {
        int j = i / NLP, l = i % NLP;
        sA[j][l] = pack2(g_aconst[(s0 + 2 * l) * 64 + j],
                         g_aconst[(s0 + 2 * l + 1) * 64 + j]);
    }
    if (tid < SCHUNK) ssrc[tid] = g_src[s0 + tid];
    __syncthreads();

    const int t = blockIdx.x * TPB + tid;
    if (t >= T) return;

    const float invL = 1.0f / refL[0];
    const float tx = tp[3 * t] * invL;
    const float ty = tp[3 * t + 1] * invL;
    const float tz = tp[3 * t + 2] * invL;

    // ---- front: geometry for 6 sources; keep only ir + packed (log2r2, c)
    float ir[SCHUNK];
    ull LOGR[NLP], C[NLP];
    ull O0[NLP], O1[NLP], O2[NLP], O3[NLP];
    {
        float lr[SCHUNK], cc[SCHUNK];
        #pragma unroll
        for (int u = 0; u < SCHUNK; u++) {
            const SrcData sd = ssrc[u];
            float dx = tx - sd.x, dy = ty - sd.y, dz = tz - sd.z;
            float r2 = fmaf(dx, dx, fmaf(dy, dy, fmaf(dz, dz, 1e-16f)));
            float irr = rsqrtf(r2);
            cc[u] = (dx * sd.nhx + dy * sd.nhy + dz * sd.nhz) * irr;
            lr[u] = __log2f(r2);    // ln->log2 scale folded into w1log
            ir[u] = irr;
        }
        #pragma unroll
        for (int l = 0; l < NLP; l++) {
            LOGR[l] = pack2(lr[2*l], lr[2*l+1]);
            C[l]    = pack2(cc[2*l], cc[2*l+1]);
            O0[l] = c_wrec[0 * 10 + 9];   // b2[0]
            O1[l] = c_wrec[1 * 10 + 9];   // b2[1]
            O2[l] = c_wrec[2 * 10 + 9];   // b2[2]
            O3[l] = c_wrec[3 * 10 + 9];   // b2[3]
        }
    }

    // ---- fused MLP: Horner in c; weights via uniform constant loads,
    //      per-(chunk,j) constant via one LDS per j-lane, serving 6 pairs
    #pragma unroll 4
    for (int j = 0; j < 64; j++) {
        const ulonglong2* wp = (const ulonglong2*)&c_wrec[j * 10];
        ulonglong2 p0 = wp[0];   // w1log, q1
        ulonglong2 p1 = wp[1];   // q2, q3
        ulonglong2 p2 = wp[2];   // q4, v0
        ulonglong2 p3 = wp[3];   // v1, v2
        ull v3 = c_wrec[j * 10 + 8];
        #pragma unroll
        for (int l = 0; l < NLP; l++) {
            // base = A + log2r2*w1log ; poly = c*(q1 + c*(q2 + c*(q3 + c*q4)))
            ull base = fma2(LOGR[l], p0.x, sA[j][l]);
            ull pq = fma2(C[l], p2.x, p1.y);      // q3 + c*q4
            pq = fma2(C[l], pq, p1.x);            // q2 + ...
            pq = fma2(C[l], pq, p0.y);            // q1 + ...
            ull b = fma2(C[l], pq, base);
            ull h = silu_packed(b);               // silu(2b) = b + b*tanh(b)
            O0[l] = fma2(h, p2.y, O0[l]);
            O1[l] = fma2(h, p3.x, O1[l]);
            O2[l] = fma2(h, p3.y, O2[l]);
            O3[l] = fma2(h, v3, O3[l]);
        }
    }

    // ---- epilogue: tanh (HW approx), decay weighting, accumulate
    float o0[SCHUNK], o1[SCHUNK], o2[SCHUNK], o3[SCHUNK];
    #pragma unroll
    for (int l = 0; l < NLP; l++) {
        unpack2(O0[l], o0[2*l], o0[2*l+1]);
        unpack2(O1[l], o1[2*l], o1[2*l+1]);
        unpack2(O2[l], o2[2*l], o2[2*l+1]);
        unpack2(O3[l], o3[2*l], o3[2*l+1]);
    }

    float acc0 = 0.f, acc1 = 0.f, acc2 = 0.f, acc3 = 0.f;
    #pragma unroll
    for (int u = 0; u < SCHUNK; u++) {
        const SrcData sd = ssrc[u];
        float t0 = tanh_apx(o0[u]);
        float t1 = tanh_apx(o1[u]);
        float t2 = tanh_apx(o2[u]);
        float t3 = tanh_apx(o3[u]);
        float irr = ir[u];
        float dx = tx - sd.x, dy = ty - sd.y, dz = tz - sd.z;
        float wir = sd.w * irr;              // w * inv_r   (scalar decay, D=3)
        acc0 = fmaf(wir, t0, acc0);
        float wv = wir * irr;                // w * inv_r^2 (vector decay)
        float rhx = dx * irr, rhy = dy * irr, rhz = dz * irr;
        float cx = rhy * sd.nhz - rhz * sd.nhy;
        float cy = rhz * sd.nhx - rhx * sd.nhz;
        float cz = rhx * sd.nhy - rhy * sd.nhx;
        acc1 = fmaf(wv, fmaf(t1, rhx, fmaf(t2, sd.nhx, t3 * cx)), acc1);
        acc2 = fmaf(wv, fmaf(t1, rhy, fmaf(t2, sd.nhy, t3 * cy)), acc2);
        acc3 = fmaf(wv, fmaf(t1, rhz, fmaf(t2, sd.nhz, t3 * cz)), acc3);
    }

    // one vector reduction instead of 4 scalar atomics
    asm volatile("red.global.add.v4.f32 [%0], {%1, %2, %3, %4};"
                 :: "l"(out + 4 * t), "f"(acc0), "f"(acc1), "f"(acc2), "f"(acc3)
                 : "memory");
}

extern "C" void kernel_launch(void* const* d_in, const int* in_sizes, int n_in,
                              void* d_out, int out_size) {
    const float* refL = (const float*)d_in[0];
    const float* sp   = (const float*)d_in[1];
    const float* tp   = (const float*)d_in[2];
    const float* ss   = (const float*)d_in[3];
    const float* sa   = (const float*)d_in[4];
    const float* sn   = (const float*)d_in[5];
    const float* W1   = (const float*)d_in[6];
    const float* b1   = (const float*)d_in[7];
    const float* W2   = (const float*)d_in[8];
    const float* b2   = (const float*)d_in[9];
    float* out = (float*)d_out;

    int S = in_sizes[3];          // source_strengths element count
    int T = in_sizes[2] / 3;      // target_points is (T, 3)
    int SP = ((S + SCHUNK - 1) / SCHUNK) * SCHUNK;   // pad to multiple of 6
    if (SP > SMAX) SP = SMAX;

    prep_all<<<SP, 64>>>(refL, sp, ss, sa, sn, W1, b1, W2, b2, out, S, SP, out_size);

    // copy folded weight record into the constant bank (D2D, graph-capturable)
    void* wsrc = nullptr;
    cudaGetSymbolAddress(&wsrc, g_wrec);
    cudaMemcpyToSymbolAsync(c_wrec, wsrc, sizeof(ull) * 64 * 10, 0,
                            cudaMemcpyDeviceToDevice);

    dim3 grid((T + TPB - 1) / TPB, SP / SCHUNK);
    bh_kernel<<<grid, TPB>>>(refL, tp, out, T);
}